// round 10
// baseline (speedup 1.0000x reference)
#include <cuda_runtime.h>
#include <stdint.h>
#include <stddef.h>
#include <math.h>

#define SMS 132
#define SMEMB (3 * 128 * SMS * 4)

__device__ double d_Ad[128 * 128];
__device__ float  d_Af[128 * 128];
__device__ float  d_W3[128 * 128];
__device__ double d_ud[128];
__device__ float  d_uf[128];
__device__ float  d_vf[128];
__device__ float  d_yf[128];
__device__ float  d_wf;
__device__ uint2  d_keys[127];
__device__ float  d_SC[2048u * 128u * 128u];      // scores [b][m][n]
__device__ float  d_G[127u * 2048u * 128u];       // gumbel [t][b*128+n]

__device__ __forceinline__ uint32_t rotl32(uint32_t v, uint32_t s) {
    return (v << s) | (v >> (32u - s));
}
__device__ __forceinline__ void tf2x32(uint32_t k0, uint32_t k1, uint32_t& x0, uint32_t& x1) {
    uint32_t k2 = k0 ^ k1 ^ 0x1BD11BDAu;
    x0 += k0; x1 += k1;
#define TFR(r) { x0 += x1; x1 = rotl32(x1, r); x1 ^= x0; }
    TFR(13u) TFR(15u) TFR(26u) TFR(6u)  x0 += k1; x1 += k2 + 1u;
    TFR(17u) TFR(29u) TFR(16u) TFR(24u) x0 += k2; x1 += k0 + 2u;
    TFR(13u) TFR(15u) TFR(26u) TFR(6u)  x0 += k0; x1 += k1 + 3u;
    TFR(17u) TFR(29u) TFR(16u) TFR(24u) x0 += k1; x1 += k2 + 4u;
    TFR(13u) TFR(15u) TFR(26u) TFR(6u)  x0 += k2; x1 += k0 + 5u;
#undef TFR
}

// XLA EmitTanh rational approximation (f32)
__device__ __forceinline__ float xla_tanh(float x) {
    const float cl = 7.99881172180175781f;
    float xc = fminf(fmaxf(x, -cl), cl);
    float x2 = xc * xc;
    float p = fmaf(x2, -2.76076847742355e-16f, 2.00018790482477e-13f);
    p = fmaf(x2, p, -8.60467152213735e-11f);
    p = fmaf(x2, p,  5.12229709037114e-08f);
    p = fmaf(x2, p,  1.48572235717979e-05f);
    p = fmaf(x2, p,  6.37261928875436e-04f);
    p = fmaf(x2, p,  4.89352455891786e-03f);
    float num = xc * p;
    float q = fmaf(x2, 1.19825839466702e-06f, 1.18534705686654e-04f);
    q = fmaf(x2, q, 2.26843463243900e-03f);
    q = fmaf(x2, q, 4.89352518554385e-03f);
    float r = num / q;
    return (fabsf(x) < 0.0004f) ? x : r;
}

#define KAHAN(s, c0, prod) { float _y = (prod) - (c0); float _t = (s) + _y; (c0) = (_t - (s)) - _y; (s) = _t; }

typedef unsigned long long u64t;
__device__ __forceinline__ u64t pk2(float lo, float hi) {
    u64t r; asm("mov.b64 %0,{%1,%2};" : "=l"(r) : "f"(lo), "f"(hi)); return r;
}
__device__ __forceinline__ u64t fma2(u64t a, u64t b, u64t c) {
    u64t d; asm("fma.rn.f32x2 %0,%1,%2,%3;" : "=l"(d) : "l"(a), "l"(b), "l"(c)); return d;
}
__device__ __forceinline__ void upk2(u64t v, float& lo, float& hi) {
    asm("mov.b64 {%0,%1},%2;" : "=f"(lo), "=f"(hi) : "l"(v));
}

// partitionable (foldlike) split: key[t] = (bits1, bits2) = threefry(key, hi=0, lo=t)
__global__ void keys_kernel() {
    int t = threadIdx.x;
    if (t < 127) {
        uint32_t x0 = 0u, x1 = (uint32_t)t;
        tf2x32(0u, 42u, x0, x1);
        d_keys[t] = make_uint2(x0, x1);
    }
}

// partitionable random_bits, 32-bit: bits = bits1 ^ bits2 (XOR of both output words)
__global__ void gumbel_kernel() {
    uint32_t gid = blockIdx.x * 256u + threadIdx.x;   // 127 * 262144 threads
    uint32_t t = gid >> 18, j = gid & 262143u;
    uint2 kk = d_keys[t];
    uint32_t x0 = 0u, x1 = j;                          // count j -> (hi=0, lo=j)
    tf2x32(kk.x, kk.y, x0, x1);
    uint32_t bits = x0 ^ x1;                           // <-- the fix
    const float TINY = 1.17549435082228751e-38f;
    float f = __uint_as_float((bits >> 9) | 0x3f800000u) - 1.0f;
    float u = fmaxf(TINY, f + TINY);
    d_G[(size_t)t * 262144u + j] = -logf(-logf(u));
}

__global__ void setup1_kernel(const float* __restrict__ Wq, const float* __restrict__ bq,
                              const float* __restrict__ Wk, const float* __restrict__ bk) {
    int blk = blockIdx.x, t = threadIdx.x;
    if (blk < 128) {
        const float* wqr = Wq + blk * 128;
        const float* wkr = Wk + t * 128;
        double s = 0.0;
        for (int j = 0; j < 128; j++) s += (double)wqr[j] * (double)wkr[j];
        d_Ad[blk * 128 + t] = s;
        d_Af[blk * 128 + t] = (float)s;
    } else {
        double su = 0.0, sv = 0.0;
        for (int j = 0; j < 128; j++) {
            su += (double)Wq[t * 128 + j] * (double)bk[j];
            sv += (double)bq[j] * (double)Wk[t * 128 + j];
        }
        d_ud[t] = su; d_uf[t] = (float)su; d_vf[t] = (float)sv;
        if (t == 0) {
            double sw = 0.0;
            for (int j = 0; j < 128; j++) sw += (double)bq[j] * (double)bk[j];
            d_wf = (float)sw;
        }
    }
}

__global__ void setup2_kernel(const float* __restrict__ Wc) {
    int blk = blockIdx.x, t = threadIdx.x;
    if (blk < 128) {
        const float* wcr = Wc + (128 + blk) * 128;
        double s = 0.0;
        for (int j = 0; j < 128; j++) s += (double)wcr[j] * d_Ad[j * 128 + t];
        d_W3[blk * 128 + t] = (float)s;
    } else {
        const float* wcr = Wc + (128 + t) * 128;
        double s = 0.0;
        for (int j = 0; j < 128; j++) s += (double)wcr[j] * d_ud[j];
        d_yf[t] = (float)s;
    }
}

__global__ void __launch_bounds__(256, 1) scores_kernel(
    const float* __restrict__ h, const float* __restrict__ graph,
    const float* __restrict__ Wc, const float* __restrict__ bc)
{
    extern __shared__ float smem[];
    float* hT  = smem;                 // hT[l][n] = h[b][n][l]
    float* W3s = smem + 128 * SMS;     // W3 row-major [k][l]
    float* Gt  = smem + 2 * 128 * SMS; // Gt[l][m] = G[m][l]
    __shared__ float Psh[128], PAsh[128], Ssh[128], Rsh[128];
    __shared__ float cbsh;

    const int b = blockIdx.x, tid = threadIdx.x;
    const int tx = tid & 15, ty = tid >> 4;
    const int r0 = ty << 3, c0 = tx << 2, c1 = 64 + (tx << 2);
    const float* __restrict__ hb = h + ((size_t)b << 14);

    {   // load h transposed
        int row = tid >> 1, cb0 = (tid & 1) << 6;
        const float4* src = (const float4*)(hb + row * 128 + cb0);
#pragma unroll
        for (int q = 0; q < 16; q++) {
            float4 vv = src[q];
            int l = cb0 + 4 * q;
            hT[(l + 0) * SMS + row] = vv.x; hT[(l + 1) * SMS + row] = vv.y;
            hT[(l + 2) * SMS + row] = vv.z; hT[(l + 3) * SMS + row] = vv.w;
        }
        const float4* w3 = (const float4*)d_W3;
        for (int i = tid; i < 128 * 32; i += 256) {
            float4 vv = w3[i];
            *(float4*)&W3s[(i >> 5) * SMS + ((i & 31) << 2)] = vv;
        }
    }
    __syncthreads();

    if (tid < 128) {    // P[j] = graph_b . Wc_top[:,j] + bc[j]
        const float* g = graph + (b << 7);
        float s = 0.f, cc = 0.f;
        for (int i = 0; i < 128; i++) { float pr = g[i] * Wc[i * 128 + tid]; KAHAN(s, cc, pr) }
        Psh[tid] = s + bc[tid];
    }
    __syncthreads();
    if (tid < 128) {    // PA[l] + v[l]
        float s = 0.f, cc = 0.f;
        for (int j = 0; j < 128; j++) { float pr = Psh[j] * d_Af[j * 128 + tid]; KAHAN(s, cc, pr) }
        PAsh[tid] = s + d_vf[tid];
    } else if (tid == 128) {
        float s = 0.f, cc = 0.f;
        for (int j = 0; j < 128; j++) { float pr = Psh[j] * d_uf[j]; KAHAN(s, cc, pr) }
        cbsh = s + d_wf;
    }
    __syncthreads();
    if (tid < 128) {    // S[n]
        float s = 0.f, cc = 0.f;
        for (int l = 0; l < 128; l++) { float pr = PAsh[l] * hT[l * SMS + tid]; KAHAN(s, cc, pr) }
        Ssh[tid] = s;
    } else {            // R[m]
        int m = tid - 128;
        float s = 0.f, cc = 0.f;
        for (int i = 0; i < 128; i++) { float pr = d_yf[i] * hT[i * SMS + m]; KAHAN(s, cc, pr) }
        Rsh[m] = s + cbsh;
    }
    __syncthreads();

    u64t acc[8][4];
#pragma unroll
    for (int j = 0; j < 8; j++)
#pragma unroll
        for (int p = 0; p < 4; p++) acc[j][p] = 0ull;

    // phase 1: Gt[l][m] = sum_k W3s[k][l] * hT[k][m]
#pragma unroll 2
    for (int k = 0; k < 128; k++) {
        float4 A0 = *(const float4*)&W3s[k * SMS + r0];
        float4 A1 = *(const float4*)&W3s[k * SMS + r0 + 4];
        float4 B0 = *(const float4*)&hT[k * SMS + c0];
        float4 B1 = *(const float4*)&hT[k * SMS + c1];
        float av[8] = {A0.x, A0.y, A0.z, A0.w, A1.x, A1.y, A1.z, A1.w};
        u64t pb[4] = {pk2(B0.x, B0.y), pk2(B0.z, B0.w), pk2(B1.x, B1.y), pk2(B1.z, B1.w)};
#pragma unroll
        for (int j = 0; j < 8; j++) {
            u64t pa = pk2(av[j], av[j]);
#pragma unroll
            for (int p = 0; p < 4; p++) acc[j][p] = fma2(pa, pb[p], acc[j][p]);
        }
    }
#pragma unroll
    for (int j = 0; j < 8; j++) {
        float4 o0, o1;
        upk2(acc[j][0], o0.x, o0.y); upk2(acc[j][1], o0.z, o0.w);
        upk2(acc[j][2], o1.x, o1.y); upk2(acc[j][3], o1.z, o1.w);
        *(float4*)&Gt[(r0 + j) * SMS + c0] = o0;
        *(float4*)&Gt[(r0 + j) * SMS + c1] = o1;
    }
    __syncthreads();

#pragma unroll
    for (int j = 0; j < 8; j++)
#pragma unroll
        for (int p = 0; p < 4; p++) acc[j][p] = 0ull;

    // phase 2: pair[m][n] = sum_l Gt[l][m] * hT[l][n]
#pragma unroll 2
    for (int l = 0; l < 128; l++) {
        float4 A0 = *(const float4*)&Gt[l * SMS + r0];
        float4 A1 = *(const float4*)&Gt[l * SMS + r0 + 4];
        float4 B0 = *(const float4*)&hT[l * SMS + c0];
        float4 B1 = *(const float4*)&hT[l * SMS + c1];
        float av[8] = {A0.x, A0.y, A0.z, A0.w, A1.x, A1.y, A1.z, A1.w};
        u64t pb[4] = {pk2(B0.x, B0.y), pk2(B0.z, B0.w), pk2(B1.x, B1.y), pk2(B1.z, B1.w)};
#pragma unroll
        for (int j = 0; j < 8; j++) {
            u64t pa = pk2(av[j], av[j]);
#pragma unroll
            for (int p = 0; p < 4; p++) acc[j][p] = fma2(pa, pb[p], acc[j][p]);
        }
    }

    float* scb = d_SC + ((size_t)b << 14);
#pragma unroll
    for (int j = 0; j < 8; j++) {
        int m = r0 + j;
        float rr = Rsh[m];
        float v[8];
        upk2(acc[j][0], v[0], v[1]); upk2(acc[j][1], v[2], v[3]);
        upk2(acc[j][2], v[4], v[5]); upk2(acc[j][3], v[6], v[7]);
        float o[8];
#pragma unroll
        for (int jj = 0; jj < 8; jj++) {
            int n = (jj < 4) ? (c0 + jj) : (c1 + jj - 4);
            o[jj] = 10.0f * xla_tanh((v[jj] + (rr + Ssh[n])) * 0.03125f);
        }
        *(float4*)&scb[m * 128 + c0] = make_float4(o[0], o[1], o[2], o[3]);
        *(float4*)&scb[m * 128 + c1] = make_float4(o[4], o[5], o[6], o[7]);
    }
}

__global__ void __launch_bounds__(128) decode_kernel(float* __restrict__ out, int out_size) {
    const int b = blockIdx.x, n = threadIdx.x;
    __shared__ float sMasked[128];
    __shared__ float rv[4], rm[4], rs[4];
    __shared__ int   ri[4];
    __shared__ int   sNxt;
    __shared__ float sMax;
    const float NEG = __int_as_float(0xff800000);

    bool visited = (n == 0);
    float logp = 0.0f;
    if (n == 0) out[b * 128] = 0.0f;

    const float* scRow = d_SC + ((size_t)b << 14);
    float sc = scRow[n];                       // cur = 0
    float gcur = d_G[(size_t)b * 128u + n];    // t = 0
    int lane = n & 31, w = n >> 5;

    for (int t = 0; t < 127; t++) {
        float gnext = (t < 126) ? d_G[(size_t)(t + 1) * 262144u + (size_t)b * 128u + n] : 0.f;
        float masked = visited ? NEG : sc;
        sMasked[n] = masked;
        float v = masked + gcur;
        int idx = n;
        float mm = masked;
#pragma unroll
        for (int o = 16; o > 0; o >>= 1) {
            float ov = __shfl_xor_sync(0xffffffffu, v, o);
            int   oi = __shfl_xor_sync(0xffffffffu, idx, o);
            float om = __shfl_xor_sync(0xffffffffu, mm, o);
            if (ov > v || (ov == v && oi < idx)) { v = ov; idx = oi; }
            mm = fmaxf(mm, om);
        }
        if (lane == 0) { rv[w] = v; ri[w] = idx; rm[w] = mm; }
        __syncthreads();
        if (n == 0) {
            float bv = rv[0]; int bi = ri[0]; float bm = rm[0];
#pragma unroll
            for (int q = 1; q < 4; q++) {
                if (rv[q] > bv || (rv[q] == bv && ri[q] < bi)) { bv = rv[q]; bi = ri[q]; }
                bm = fmaxf(bm, rm[q]);
            }
            sNxt = bi; sMax = bm;
        }
        __syncthreads();
        int nxt = sNxt;
        float mx = sMax;
        float scn = scRow[(nxt << 7) + n];     // prefetch next score row
        float pickSc = (n == 0) ? sMasked[nxt] : 0.f;
        float e = expf(masked - mx);
#pragma unroll
        for (int o = 16; o > 0; o >>= 1) e += __shfl_xor_sync(0xffffffffu, e, o);
        if (lane == 0) rs[w] = e;
        __syncthreads();
        if (n == 0) {
            float s = rs[0] + rs[1] + rs[2] + rs[3];
            logp += pickSc - mx - logf(s);
            out[b * 128 + t + 1] = (float)nxt;
        }
        visited = visited || (n == nxt);
        sc = scn;
        gcur = gnext;
    }
    if (n == 0 && out_size >= 2048 * 128 + 2048) out[2048 * 128 + b] = logp;
}

extern "C" void kernel_launch(void* const* d_in, const int* in_sizes, int n_in,
                              void* d_out, int out_size) {
    const float* h     = (const float*)d_in[0];
    const float* graph = (const float*)d_in[1];
    const float* Wq    = (const float*)d_in[2];
    const float* bq    = (const float*)d_in[3];
    const float* Wk    = (const float*)d_in[4];
    const float* bk    = (const float*)d_in[5];
    const float* Wc    = (const float*)d_in[8];
    const float* bc    = (const float*)d_in[9];
    float* out = (float*)d_out;

    setup1_kernel<<<129, 128>>>(Wq, bq, Wk, bk);
    setup2_kernel<<<129, 128>>>(Wc);
    keys_kernel<<<1, 128>>>();
    gumbel_kernel<<<130048, 256>>>();
    cudaFuncSetAttribute(scores_kernel, cudaFuncAttributeMaxDynamicSharedMemorySize, SMEMB);
    scores_kernel<<<2048, 256, SMEMB>>>(h, graph, Wc, bc);
    decode_kernel<<<2048, 128>>>(out, out_size);
}

// round 14
// speedup vs baseline: 1.0966x; 1.0966x over previous
#include <cuda_runtime.h>
#include <stdint.h>
#include <stddef.h>
#include <math.h>

#define SMS 132
#define SMEMB (3 * 128 * SMS * 4)

__device__ double d_Ad[128 * 128];
__device__ float  d_Af[128 * 128];
__device__ float  d_W3[128 * 128];
__device__ double d_ud[128];
__device__ float  d_uf[128];
__device__ float  d_vf[128];
__device__ float  d_yf[128];
__device__ float  d_wf;
__device__ uint2  d_keys[127];
__device__ float  d_SC[2048u * 128u * 128u];      // scores [b][m][n]

__device__ __forceinline__ uint32_t rotl32(uint32_t v, uint32_t s) {
    return (v << s) | (v >> (32u - s));
}
__device__ __forceinline__ void tf2x32(uint32_t k0, uint32_t k1, uint32_t& x0, uint32_t& x1) {
    uint32_t k2 = k0 ^ k1 ^ 0x1BD11BDAu;
    x0 += k0; x1 += k1;
#define TFR(r) { x0 += x1; x1 = rotl32(x1, r); x1 ^= x0; }
    TFR(13u) TFR(15u) TFR(26u) TFR(6u)  x0 += k1; x1 += k2 + 1u;
    TFR(17u) TFR(29u) TFR(16u) TFR(24u) x0 += k2; x1 += k0 + 2u;
    TFR(13u) TFR(15u) TFR(26u) TFR(6u)  x0 += k0; x1 += k1 + 3u;
    TFR(17u) TFR(29u) TFR(16u) TFR(24u) x0 += k1; x1 += k2 + 4u;
    TFR(13u) TFR(15u) TFR(26u) TFR(6u)  x0 += k2; x1 += k0 + 5u;
#undef TFR
}

// partitionable random_bits (32-bit): bits = x0out ^ x1out of threefry(key, hi=0, lo=j)
__device__ __forceinline__ float gumbel_one(uint2 kk, uint32_t j) {
    uint32_t x0 = 0u, x1 = j;
    tf2x32(kk.x, kk.y, x0, x1);
    uint32_t bits = x0 ^ x1;
    const float TINY = 1.17549435082228751e-38f;
    float f = __uint_as_float((bits >> 9) | 0x3f800000u) - 1.0f;
    float u = fmaxf(TINY, f + TINY);
    return -logf(-logf(u));
}

// XLA EmitTanh rational approximation (f32)
__device__ __forceinline__ float xla_tanh(float x) {
    const float cl = 7.99881172180175781f;
    float xc = fminf(fmaxf(x, -cl), cl);
    float x2 = xc * xc;
    float p = fmaf(x2, -2.76076847742355e-16f, 2.00018790482477e-13f);
    p = fmaf(x2, p, -8.60467152213735e-11f);
    p = fmaf(x2, p,  5.12229709037114e-08f);
    p = fmaf(x2, p,  1.48572235717979e-05f);
    p = fmaf(x2, p,  6.37261928875436e-04f);
    p = fmaf(x2, p,  4.89352455891786e-03f);
    float num = xc * p;
    float q = fmaf(x2, 1.19825839466702e-06f, 1.18534705686654e-04f);
    q = fmaf(x2, q, 2.26843463243900e-03f);
    q = fmaf(x2, q, 4.89352518554385e-03f);
    float r = num / q;
    return (fabsf(x) < 0.0004f) ? x : r;
}

#define KAHAN(s, c0, prod) { float _y = (prod) - (c0); float _t = (s) + _y; (c0) = (_t - (s)) - _y; (s) = _t; }

typedef unsigned long long u64t;
__device__ __forceinline__ u64t pk2(float lo, float hi) {
    u64t r; asm("mov.b64 %0,{%1,%2};" : "=l"(r) : "f"(lo), "f"(hi)); return r;
}
__device__ __forceinline__ u64t fma2(u64t a, u64t b, u64t c) {
    u64t d; asm("fma.rn.f32x2 %0,%1,%2,%3;" : "=l"(d) : "l"(a), "l"(b), "l"(c)); return d;
}
__device__ __forceinline__ void upk2(u64t v, float& lo, float& hi) {
    asm("mov.b64 {%0,%1},%2;" : "=f"(lo), "=f"(hi) : "l"(v));
}

// partitionable (foldlike) split: key[t] = (x0out, x1out) = threefry(key, hi=0, lo=t)
__global__ void keys_kernel() {
    int t = threadIdx.x;
    if (t < 127) {
        uint32_t x0 = 0u, x1 = (uint32_t)t;
        tf2x32(0u, 42u, x0, x1);
        d_keys[t] = make_uint2(x0, x1);
    }
}

__global__ void setup1_kernel(const float* __restrict__ Wq, const float* __restrict__ bq,
                              const float* __restrict__ Wk, const float* __restrict__ bk) {
    int blk = blockIdx.x, t = threadIdx.x;
    if (blk < 128) {
        const float* wqr = Wq + blk * 128;
        const float* wkr = Wk + t * 128;
        double s = 0.0;
        for (int j = 0; j < 128; j++) s += (double)wqr[j] * (double)wkr[j];
        d_Ad[blk * 128 + t] = s;
        d_Af[blk * 128 + t] = (float)s;
    } else {
        double su = 0.0, sv = 0.0;
        for (int j = 0; j < 128; j++) {
            su += (double)Wq[t * 128 + j] * (double)bk[j];
            sv += (double)bq[j] * (double)Wk[t * 128 + j];
        }
        d_ud[t] = su; d_uf[t] = (float)su; d_vf[t] = (float)sv;
        if (t == 0) {
            double sw = 0.0;
            for (int j = 0; j < 128; j++) sw += (double)bq[j] * (double)bk[j];
            d_wf = (float)sw;
        }
    }
}

__global__ void setup2_kernel(const float* __restrict__ Wc) {
    int blk = blockIdx.x, t = threadIdx.x;
    if (blk < 128) {
        const float* wcr = Wc + (128 + blk) * 128;
        double s = 0.0;
        for (int j = 0; j < 128; j++) s += (double)wcr[j] * d_Ad[j * 128 + t];
        d_W3[blk * 128 + t] = (float)s;
    } else {
        const float* wcr = Wc + (128 + t) * 128;
        double s = 0.0;
        for (int j = 0; j < 128; j++) s += (double)wcr[j] * d_ud[j];
        d_yf[t] = (float)s;
    }
}

__global__ void __launch_bounds__(256, 1) scores_kernel(
    const float* __restrict__ h, const float* __restrict__ graph,
    const float* __restrict__ Wc, const float* __restrict__ bc)
{
    extern __shared__ float smem[];
    float* hT  = smem;                 // hT[l][n] = h[b][n][l]
    float* W3s = smem + 128 * SMS;     // W3 row-major [k][l]
    float* Gt  = smem + 2 * 128 * SMS; // Gt[l][m] = G[m][l]
    __shared__ float Psh[128], PAsh[128], Ssh[128], Rsh[128];
    __shared__ float cbsh;

    const int b = blockIdx.x, tid = threadIdx.x;
    const int tx = tid & 15, ty = tid >> 4;
    const int r0 = ty << 3, c0 = tx << 2, c1 = 64 + (tx << 2);
    const float* __restrict__ hb = h + ((size_t)b << 14);

    {   // load h transposed
        int row = tid >> 1, cb0 = (tid & 1) << 6;
        const float4* src = (const float4*)(hb + row * 128 + cb0);
#pragma unroll
        for (int q = 0; q < 16; q++) {
            float4 vv = src[q];
            int l = cb0 + 4 * q;
            hT[(l + 0) * SMS + row] = vv.x; hT[(l + 1) * SMS + row] = vv.y;
            hT[(l + 2) * SMS + row] = vv.z; hT[(l + 3) * SMS + row] = vv.w;
        }
        const float4* w3 = (const float4*)d_W3;
        for (int i = tid; i < 128 * 32; i += 256) {
            float4 vv = w3[i];
            *(float4*)&W3s[(i >> 5) * SMS + ((i & 31) << 2)] = vv;
        }
    }
    __syncthreads();

    if (tid < 128) {    // P[j] = graph_b . Wc_top[:,j] + bc[j]
        const float* g = graph + (b << 7);
        float s = 0.f, cc = 0.f;
        for (int i = 0; i < 128; i++) { float pr = g[i] * Wc[i * 128 + tid]; KAHAN(s, cc, pr) }
        Psh[tid] = s + bc[tid];
    }
    __syncthreads();
    if (tid < 128) {    // PA[l] + v[l]
        float s = 0.f, cc = 0.f;
        for (int j = 0; j < 128; j++) { float pr = Psh[j] * d_Af[j * 128 + tid]; KAHAN(s, cc, pr) }
        PAsh[tid] = s + d_vf[tid];
    } else if (tid == 128) {
        float s = 0.f, cc = 0.f;
        for (int j = 0; j < 128; j++) { float pr = Psh[j] * d_uf[j]; KAHAN(s, cc, pr) }
        cbsh = s + d_wf;
    }
    __syncthreads();
    if (tid < 128) {    // S[n]
        float s = 0.f, cc = 0.f;
        for (int l = 0; l < 128; l++) { float pr = PAsh[l] * hT[l * SMS + tid]; KAHAN(s, cc, pr) }
        Ssh[tid] = s;
    } else {            // R[m]
        int m = tid - 128;
        float s = 0.f, cc = 0.f;
        for (int i = 0; i < 128; i++) { float pr = d_yf[i] * hT[i * SMS + m]; KAHAN(s, cc, pr) }
        Rsh[m] = s + cbsh;
    }
    __syncthreads();

    u64t acc[8][4];
#pragma unroll
    for (int j = 0; j < 8; j++)
#pragma unroll
        for (int p = 0; p < 4; p++) acc[j][p] = 0ull;

    // phase 1: Gt[l][m] = sum_k W3s[k][l] * hT[k][m]
#pragma unroll 2
    for (int k = 0; k < 128; k++) {
        float4 A0 = *(const float4*)&W3s[k * SMS + r0];
        float4 A1 = *(const float4*)&W3s[k * SMS + r0 + 4];
        float4 B0 = *(const float4*)&hT[k * SMS + c0];
        float4 B1 = *(const float4*)&hT[k * SMS + c1];
        float av[8] = {A0.x, A0.y, A0.z, A0.w, A1.x, A1.y, A1.z, A1.w};
        u64t pb[4] = {pk2(B0.x, B0.y), pk2(B0.z, B0.w), pk2(B1.x, B1.y), pk2(B1.z, B1.w)};
#pragma unroll
        for (int j = 0; j < 8; j++) {
            u64t pa = pk2(av[j], av[j]);
#pragma unroll
            for (int p = 0; p < 4; p++) acc[j][p] = fma2(pa, pb[p], acc[j][p]);
        }
    }
#pragma unroll
    for (int j = 0; j < 8; j++) {
        float4 o0, o1;
        upk2(acc[j][0], o0.x, o0.y); upk2(acc[j][1], o0.z, o0.w);
        upk2(acc[j][2], o1.x, o1.y); upk2(acc[j][3], o1.z, o1.w);
        *(float4*)&Gt[(r0 + j) * SMS + c0] = o0;
        *(float4*)&Gt[(r0 + j) * SMS + c1] = o1;
    }
    __syncthreads();

#pragma unroll
    for (int j = 0; j < 8; j++)
#pragma unroll
        for (int p = 0; p < 4; p++) acc[j][p] = 0ull;

    // phase 2: pair[m][n] = sum_l Gt[l][m] * hT[l][n]
#pragma unroll 2
    for (int l = 0; l < 128; l++) {
        float4 A0 = *(const float4*)&Gt[l * SMS + r0];
        float4 A1 = *(const float4*)&Gt[l * SMS + r0 + 4];
        float4 B0 = *(const float4*)&hT[l * SMS + c0];
        float4 B1 = *(const float4*)&hT[l * SMS + c1];
        float av[8] = {A0.x, A0.y, A0.z, A0.w, A1.x, A1.y, A1.z, A1.w};
        u64t pb[4] = {pk2(B0.x, B0.y), pk2(B0.z, B0.w), pk2(B1.x, B1.y), pk2(B1.z, B1.w)};
#pragma unroll
        for (int j = 0; j < 8; j++) {
            u64t pa = pk2(av[j], av[j]);
#pragma unroll
            for (int p = 0; p < 4; p++) acc[j][p] = fma2(pa, pb[p], acc[j][p]);
        }
    }

    float* scb = d_SC + ((size_t)b << 14);
#pragma unroll
    for (int j = 0; j < 8; j++) {
        int m = r0 + j;
        float rr = Rsh[m];
        float v[8];
        upk2(acc[j][0], v[0], v[1]); upk2(acc[j][1], v[2], v[3]);
        upk2(acc[j][2], v[4], v[5]); upk2(acc[j][3], v[6], v[7]);
        float o[8];
#pragma unroll
        for (int jj = 0; jj < 8; jj++) {
            int n = (jj < 4) ? (c0 + jj) : (c1 + jj - 4);
            o[jj] = 10.0f * xla_tanh((v[jj] + (rr + Ssh[n])) * 0.03125f);
        }
        *(float4*)&scb[m * 128 + c0] = make_float4(o[0], o[1], o[2], o[3]);
        *(float4*)&scb[m * 128 + c1] = make_float4(o[4], o[5], o[6], o[7]);
    }
}

// Single-warp decode: 32 threads, 4 nodes each; no __syncthreads.
// Gumbel noise computed inline (threefry), pipelined under the score-row load.
__global__ void __launch_bounds__(32) decode_kernel(float* __restrict__ out, int out_size) {
    const int b = blockIdx.x;
    const int lane = threadIdx.x;
    const float NEG = __int_as_float(0xff800000);
    const float* __restrict__ scRow = d_SC + ((size_t)b << 14);

    unsigned visited = (lane == 0) ? 1u : 0u;       // bit i <-> node lane*4+i
    float logp = 0.0f;
    if (lane == 0) out[b * 128] = 0.0f;

    const uint32_t jbase = ((uint32_t)b << 7) + ((uint32_t)lane << 2);
    const int nbase = lane << 2;

    float4 sc = *(const float4*)(scRow + nbase);     // row of cur = 0
    float g0, g1, g2, g3;
    {
        uint2 kk = d_keys[0];
        g0 = gumbel_one(kk, jbase + 0u);
        g1 = gumbel_one(kk, jbase + 1u);
        g2 = gumbel_one(kk, jbase + 2u);
        g3 = gumbel_one(kk, jbase + 3u);
    }

    for (int t = 0; t < 127; t++) {
        float mk0 = (visited & 1u) ? NEG : sc.x;
        float mk1 = (visited & 2u) ? NEG : sc.y;
        float mk2 = (visited & 4u) ? NEG : sc.z;
        float mk3 = (visited & 8u) ? NEG : sc.w;

        // local argmax of mk+g (first index wins on ties via strict >)
        float v = mk0 + g0; int idx = nbase;
        float c;
        c = mk1 + g1; if (c > v) { v = c; idx = nbase + 1; }
        c = mk2 + g2; if (c > v) { v = c; idx = nbase + 2; }
        c = mk3 + g3; if (c > v) { v = c; idx = nbase + 3; }
        float mm = fmaxf(fmaxf(mk0, mk1), fmaxf(mk2, mk3));

#pragma unroll
        for (int o = 16; o > 0; o >>= 1) {
            float ov = __shfl_xor_sync(0xffffffffu, v, o);
            int   oi = __shfl_xor_sync(0xffffffffu, idx, o);
            float om = __shfl_xor_sync(0xffffffffu, mm, o);
            if (ov > v || (ov == v && oi < idx)) { v = ov; idx = oi; }
            mm = fmaxf(mm, om);
        }
        const int nxt = idx;           // identical across lanes after butterfly
        const float mx = mm;

        // prefetch next score row (dominant latency; below ALU overlaps it)
        float4 scn = *(const float4*)(scRow + (nxt << 7) + nbase);

        // next-step gumbel, computed under the load
        float ng0 = 0.f, ng1 = 0.f, ng2 = 0.f, ng3 = 0.f;
        if (t < 126) {
            uint2 kk = d_keys[t + 1];
            ng0 = gumbel_one(kk, jbase + 0u);
            ng1 = gumbel_one(kk, jbase + 1u);
            ng2 = gumbel_one(kk, jbase + 2u);
            ng3 = gumbel_one(kk, jbase + 3u);
        }

        // masked score at the sampled index (owner lane -> broadcast)
        int sub = nxt & 3;
        float sel = (sub == 0) ? mk0 : (sub == 1) ? mk1 : (sub == 2) ? mk2 : mk3;
        float pick = __shfl_sync(0xffffffffu, sel, nxt >> 2);

        // log-sum-exp over masked scores
        float e = expf(mk0 - mx) + expf(mk1 - mx) + expf(mk2 - mx) + expf(mk3 - mx);
#pragma unroll
        for (int o = 16; o > 0; o >>= 1) e += __shfl_xor_sync(0xffffffffu, e, o);

        logp += pick - mx - logf(e);
        if (lane == 0) out[b * 128 + t + 1] = (float)nxt;
        if ((nxt >> 2) == lane) visited |= 1u << sub;

        sc = scn;
        g0 = ng0; g1 = ng1; g2 = ng2; g3 = ng3;
    }
    if (lane == 0 && out_size >= 2048 * 128 + 2048) out[2048 * 128 + b] = logp;
}

extern "C" void kernel_launch(void* const* d_in, const int* in_sizes, int n_in,
                              void* d_out, int out_size) {
    const float* h     = (const float*)d_in[0];
    const float* graph = (const float*)d_in[1];
    const float* Wq    = (const float*)d_in[2];
    const float* bq    = (const float*)d_in[3];
    const float* Wk    = (const float*)d_in[4];
    const float* bk    = (const float*)d_in[5];
    const float* Wc    = (const float*)d_in[8];
    const float* bc    = (const float*)d_in[9];
    float* out = (float*)d_out;

    setup1_kernel<<<129, 128>>>(Wq, bq, Wk, bk);
    setup2_kernel<<<129, 128>>>(Wc);
    keys_kernel<<<1, 128>>>();
    cudaFuncSetAttribute(scores_kernel, cudaFuncAttributeMaxDynamicSharedMemorySize, SMEMB);
    scores_kernel<<<2048, 256, SMEMB>>>(h, graph, Wc, bc);
    decode_kernel<<<2048, 32>>>(out, out_size);
}

// round 15
// speedup vs baseline: 1.1539x; 1.0523x over previous
#include <cuda_runtime.h>
#include <stdint.h>
#include <stddef.h>
#include <math.h>

#define SMS 132
#define SMEMB (3 * 128 * SMS * 4)

__device__ double d_Ad[128 * 128];
__device__ float  d_Af[128 * 128];
__device__ float  d_W3[128 * 128];
__device__ double d_ud[128];
__device__ float  d_uf[128];
__device__ float  d_vf[128];
__device__ float  d_yf[128];
__device__ float  d_wf;
__device__ uint2  d_keys[127];
__device__ float  d_SC[2048u * 128u * 128u];      // scores [b][m][n]

__device__ __forceinline__ uint32_t rotl32(uint32_t v, uint32_t s) {
    return (v << s) | (v >> (32u - s));
}
__device__ __forceinline__ void tf2x32(uint32_t k0, uint32_t k1, uint32_t& x0, uint32_t& x1) {
    uint32_t k2 = k0 ^ k1 ^ 0x1BD11BDAu;
    x0 += k0; x1 += k1;
#define TFR(r) { x0 += x1; x1 = rotl32(x1, r); x1 ^= x0; }
    TFR(13u) TFR(15u) TFR(26u) TFR(6u)  x0 += k1; x1 += k2 + 1u;
    TFR(17u) TFR(29u) TFR(16u) TFR(24u) x0 += k2; x1 += k0 + 2u;
    TFR(13u) TFR(15u) TFR(26u) TFR(6u)  x0 += k0; x1 += k1 + 3u;
    TFR(17u) TFR(29u) TFR(16u) TFR(24u) x0 += k1; x1 += k2 + 4u;
    TFR(13u) TFR(15u) TFR(26u) TFR(6u)  x0 += k2; x1 += k0 + 5u;
#undef TFR
}

// partitionable random_bits (32-bit): bits = x0out ^ x1out of threefry(key, hi=0, lo=j)
__device__ __forceinline__ float gumbel_one(uint2 kk, uint32_t j) {
    uint32_t x0 = 0u, x1 = j;
    tf2x32(kk.x, kk.y, x0, x1);
    uint32_t bits = x0 ^ x1;
    const float TINY = 1.17549435082228751e-38f;
    float f = __uint_as_float((bits >> 9) | 0x3f800000u) - 1.0f;
    float u = fmaxf(TINY, f + TINY);
    return -logf(-logf(u));
}

// XLA EmitTanh rational approximation (f32)
__device__ __forceinline__ float xla_tanh(float x) {
    const float cl = 7.99881172180175781f;
    float xc = fminf(fmaxf(x, -cl), cl);
    float x2 = xc * xc;
    float p = fmaf(x2, -2.76076847742355e-16f, 2.00018790482477e-13f);
    p = fmaf(x2, p, -8.60467152213735e-11f);
    p = fmaf(x2, p,  5.12229709037114e-08f);
    p = fmaf(x2, p,  1.48572235717979e-05f);
    p = fmaf(x2, p,  6.37261928875436e-04f);
    p = fmaf(x2, p,  4.89352455891786e-03f);
    float num = xc * p;
    float q = fmaf(x2, 1.19825839466702e-06f, 1.18534705686654e-04f);
    q = fmaf(x2, q, 2.26843463243900e-03f);
    q = fmaf(x2, q, 4.89352518554385e-03f);
    float r = num / q;
    return (fabsf(x) < 0.0004f) ? x : r;
}

#define KAHAN(s, c0, prod) { float _y = (prod) - (c0); float _t = (s) + _y; (c0) = (_t - (s)) - _y; (s) = _t; }

typedef unsigned long long u64t;
__device__ __forceinline__ u64t pk2(float lo, float hi) {
    u64t r; asm("mov.b64 %0,{%1,%2};" : "=l"(r) : "f"(lo), "f"(hi)); return r;
}
__device__ __forceinline__ u64t fma2(u64t a, u64t b, u64t c) {
    u64t d; asm("fma.rn.f32x2 %0,%1,%2,%3;" : "=l"(d) : "l"(a), "l"(b), "l"(c)); return d;
}
__device__ __forceinline__ void upk2(u64t v, float& lo, float& hi) {
    asm("mov.b64 {%0,%1},%2;" : "=f"(lo), "=f"(hi) : "l"(v));
}

// 4-chain Kahan dot over 128 elems: accuracy ~Kahan, latency ~1/4 (ILP 4).
__device__ __forceinline__ float kdot128(const float* __restrict__ a, int astride,
                                         const float* __restrict__ b, int bstride) {
    float s0 = 0.f, s1 = 0.f, s2 = 0.f, s3 = 0.f;
    float c0 = 0.f, c1 = 0.f, c2 = 0.f, c3 = 0.f;
#pragma unroll 4
    for (int i = 0; i < 128; i += 4) {
        float p0 = a[(i + 0) * astride] * b[(i + 0) * bstride];
        float p1 = a[(i + 1) * astride] * b[(i + 1) * bstride];
        float p2 = a[(i + 2) * astride] * b[(i + 2) * bstride];
        float p3 = a[(i + 3) * astride] * b[(i + 3) * bstride];
        KAHAN(s0, c0, p0) KAHAN(s1, c1, p1) KAHAN(s2, c2, p2) KAHAN(s3, c3, p3)
    }
    return (s0 + s1) + (s2 + s3);
}

// partitionable (foldlike) split: key[t] = (x0out, x1out) = threefry(key, hi=0, lo=t)
__global__ void keys_kernel() {
    int t = threadIdx.x;
    if (t < 127) {
        uint32_t x0 = 0u, x1 = (uint32_t)t;
        tf2x32(0u, 42u, x0, x1);
        d_keys[t] = make_uint2(x0, x1);
    }
}

__global__ void setup1_kernel(const float* __restrict__ Wq, const float* __restrict__ bq,
                              const float* __restrict__ Wk, const float* __restrict__ bk) {
    int blk = blockIdx.x, t = threadIdx.x;
    if (blk < 128) {
        const float* wqr = Wq + blk * 128;
        const float* wkr = Wk + t * 128;
        double s = 0.0;
        for (int j = 0; j < 128; j++) s += (double)wqr[j] * (double)wkr[j];
        d_Ad[blk * 128 + t] = s;
        d_Af[blk * 128 + t] = (float)s;
    } else {
        double su = 0.0, sv = 0.0;
        for (int j = 0; j < 128; j++) {
            su += (double)Wq[t * 128 + j] * (double)bk[j];
            sv += (double)bq[j] * (double)Wk[t * 128 + j];
        }
        d_ud[t] = su; d_uf[t] = (float)su; d_vf[t] = (float)sv;
        if (t == 0) {
            double sw = 0.0;
            for (int j = 0; j < 128; j++) sw += (double)bq[j] * (double)bk[j];
            d_wf = (float)sw;
        }
    }
}

__global__ void setup2_kernel(const float* __restrict__ Wc) {
    int blk = blockIdx.x, t = threadIdx.x;
    if (blk < 128) {
        const float* wcr = Wc + (128 + blk) * 128;
        double s = 0.0;
        for (int j = 0; j < 128; j++) s += (double)wcr[j] * d_Ad[j * 128 + t];
        d_W3[blk * 128 + t] = (float)s;
    } else {
        const float* wcr = Wc + (128 + t) * 128;
        double s = 0.0;
        for (int j = 0; j < 128; j++) s += (double)wcr[j] * d_ud[j];
        d_yf[t] = (float)s;
    }
}

// 512 threads, 16 warps. Per thread: 8 rows x 4 cols of the 128x128 output.
// tx = tid & 31 -> col block (c0 = tx*4), ty = tid >> 5 -> row block (r0 = ty*8).
// A-operand loads are full-warp broadcasts (all lanes share ty).
__global__ void __launch_bounds__(512, 1) scores_kernel(
    const float* __restrict__ h, const float* __restrict__ graph,
    const float* __restrict__ Wc, const float* __restrict__ bc)
{
    extern __shared__ float smem[];
    float* hT  = smem;                 // hT[l][n] = h[b][n][l]
    float* W3s = smem + 128 * SMS;     // W3 row-major [k][l]
    float* Gt  = smem + 2 * 128 * SMS; // Gt[l][m] = G[m][l]
    __shared__ float Psh[128], PAsh[128], Ssh[128], Rsh[128];
    __shared__ float cbsh;

    const int b = blockIdx.x, tid = threadIdx.x;
    const int tx = tid & 31, ty = tid >> 5;
    const int r0 = ty << 3, c0 = tx << 2;
    const float* __restrict__ hb = h + ((size_t)b << 14);

    {   // load h transposed (512 threads: 128 rows x 4 chunks of 32 floats)
        int row = tid >> 2, cb0 = (tid & 3) << 5;
        const float4* src = (const float4*)(hb + row * 128 + cb0);
#pragma unroll
        for (int q = 0; q < 8; q++) {
            float4 vv = src[q];
            int l = cb0 + 4 * q;
            hT[(l + 0) * SMS + row] = vv.x; hT[(l + 1) * SMS + row] = vv.y;
            hT[(l + 2) * SMS + row] = vv.z; hT[(l + 3) * SMS + row] = vv.w;
        }
        const float4* w3 = (const float4*)d_W3;
        for (int i = tid; i < 128 * 32; i += 512) {
            float4 vv = w3[i];
            *(float4*)&W3s[(i >> 5) * SMS + ((i & 31) << 2)] = vv;
        }
    }
    __syncthreads();

    if (tid < 128) {    // P[j] = graph_b . Wc_top[:,j] + bc[j]
        Psh[tid] = kdot128(graph + (b << 7), 1, Wc + tid, 128) + bc[tid];
    }
    __syncthreads();
    if (tid < 128) {    // PA[l] + v[l]
        PAsh[tid] = kdot128(Psh, 1, d_Af + tid, 128) + d_vf[tid];
    } else if (tid == 128) {
        cbsh = kdot128(Psh, 1, d_uf, 1) + d_wf;
    }
    __syncthreads();
    if (tid < 128) {    // S[n]
        Ssh[tid] = kdot128(PAsh, 1, hT + tid, SMS);
    } else if (tid < 256) {  // R[m]
        int m = tid - 128;
        Rsh[m] = kdot128(d_yf, 1, hT + m, SMS) + cbsh;
    }
    __syncthreads();

    u64t acc[8][2];
#pragma unroll
    for (int j = 0; j < 8; j++) { acc[j][0] = 0ull; acc[j][1] = 0ull; }

    // phase 1: Gt[l][m] = sum_k W3s[k][l] * hT[k][m]   (l = r0+j, m = c0..c0+3)
#pragma unroll 4
    for (int k = 0; k < 128; k++) {
        float4 A0 = *(const float4*)&W3s[k * SMS + r0];
        float4 A1 = *(const float4*)&W3s[k * SMS + r0 + 4];
        float4 B0 = *(const float4*)&hT[k * SMS + c0];
        float av[8] = {A0.x, A0.y, A0.z, A0.w, A1.x, A1.y, A1.z, A1.w};
        u64t pb0 = pk2(B0.x, B0.y), pb1 = pk2(B0.z, B0.w);
#pragma unroll
        for (int j = 0; j < 8; j++) {
            u64t pa = pk2(av[j], av[j]);
            acc[j][0] = fma2(pa, pb0, acc[j][0]);
            acc[j][1] = fma2(pa, pb1, acc[j][1]);
        }
    }
#pragma unroll
    for (int j = 0; j < 8; j++) {
        float4 o;
        upk2(acc[j][0], o.x, o.y); upk2(acc[j][1], o.z, o.w);
        *(float4*)&Gt[(r0 + j) * SMS + c0] = o;
    }
    __syncthreads();

#pragma unroll
    for (int j = 0; j < 8; j++) { acc[j][0] = 0ull; acc[j][1] = 0ull; }

    // phase 2: pair[m][n] = sum_l Gt[l][m] * hT[l][n]   (m = r0+j, n = c0..c0+3)
#pragma unroll 4
    for (int l = 0; l < 128; l++) {
        float4 A0 = *(const float4*)&Gt[l * SMS + r0];
        float4 A1 = *(const float4*)&Gt[l * SMS + r0 + 4];
        float4 B0 = *(const float4*)&hT[l * SMS + c0];
        float av[8] = {A0.x, A0.y, A0.z, A0.w, A1.x, A1.y, A1.z, A1.w};
        u64t pb0 = pk2(B0.x, B0.y), pb1 = pk2(B0.z, B0.w);
#pragma unroll
        for (int j = 0; j < 8; j++) {
            u64t pa = pk2(av[j], av[j]);
            acc[j][0] = fma2(pa, pb0, acc[j][0]);
            acc[j][1] = fma2(pa, pb1, acc[j][1]);
        }
    }

    float* scb = d_SC + ((size_t)b << 14);
    float s0 = Ssh[c0], s1 = Ssh[c0 + 1], s2 = Ssh[c0 + 2], s3 = Ssh[c0 + 3];
#pragma unroll
    for (int j = 0; j < 8; j++) {
        int m = r0 + j;
        float rr = Rsh[m];
        float v0, v1, v2, v3;
        upk2(acc[j][0], v0, v1); upk2(acc[j][1], v2, v3);
        float4 o;
        o.x = 10.0f * xla_tanh((v0 + (rr + s0)) * 0.03125f);
        o.y = 10.0f * xla_tanh((v1 + (rr + s1)) * 0.03125f);
        o.z = 10.0f * xla_tanh((v2 + (rr + s2)) * 0.03125f);
        o.w = 10.0f * xla_tanh((v3 + (rr + s3)) * 0.03125f);
        *(float4*)&scb[m * 128 + c0] = o;
    }
}

// Single-warp decode: 32 threads, 4 nodes each; no __syncthreads.
// Gumbel noise computed inline (threefry), pipelined under the score-row load.
__global__ void __launch_bounds__(32) decode_kernel(float* __restrict__ out, int out_size) {
    const int b = blockIdx.x;
    const int lane = threadIdx.x;
    const float NEG = __int_as_float(0xff800000);
    const float* __restrict__ scRow = d_SC + ((size_t)b << 14);

    unsigned visited = (lane == 0) ? 1u : 0u;       // bit i <-> node lane*4+i
    float logp = 0.0f;
    if (lane == 0) out[b * 128] = 0.0f;

    const uint32_t jbase = ((uint32_t)b << 7) + ((uint32_t)lane << 2);
    const int nbase = lane << 2;

    float4 sc = *(const float4*)(scRow + nbase);     // row of cur = 0
    float g0, g1, g2, g3;
    {
        uint2 kk = d_keys[0];
        g0 = gumbel_one(kk, jbase + 0u);
        g1 = gumbel_one(kk, jbase + 1u);
        g2 = gumbel_one(kk, jbase + 2u);
        g3 = gumbel_one(kk, jbase + 3u);
    }

    for (int t = 0; t < 127; t++) {
        float mk0 = (visited & 1u) ? NEG : sc.x;
        float mk1 = (visited & 2u) ? NEG : sc.y;
        float mk2 = (visited & 4u) ? NEG : sc.z;
        float mk3 = (visited & 8u) ? NEG : sc.w;

        // local argmax of mk+g (first index wins on ties via strict >)
        float v = mk0 + g0; int idx = nbase;
        float c;
        c = mk1 + g1; if (c > v) { v = c; idx = nbase + 1; }
        c = mk2 + g2; if (c > v) { v = c; idx = nbase + 2; }
        c = mk3 + g3; if (c > v) { v = c; idx = nbase + 3; }
        float mm = fmaxf(fmaxf(mk0, mk1), fmaxf(mk2, mk3));

#pragma unroll
        for (int o = 16; o > 0; o >>= 1) {
            float ov = __shfl_xor_sync(0xffffffffu, v, o);
            int   oi = __shfl_xor_sync(0xffffffffu, idx, o);
            float om = __shfl_xor_sync(0xffffffffu, mm, o);
            if (ov > v || (ov == v && oi < idx)) { v = ov; idx = oi; }
            mm = fmaxf(mm, om);
        }
        const int nxt = idx;           // identical across lanes after butterfly
        const float mx = mm;

        // prefetch next score row (dominant latency; below ALU overlaps it)
        float4 scn = *(const float4*)(scRow + (nxt << 7) + nbase);

        // next-step gumbel, computed under the load
        float ng0 = 0.f, ng1 = 0.f, ng2 = 0.f, ng3 = 0.f;
        if (t < 126) {
            uint2 kk = d_keys[t + 1];
            ng0 = gumbel_one(kk, jbase + 0u);
            ng1 = gumbel_one(kk, jbase + 1u);
            ng2 = gumbel_one(kk, jbase + 2u);
            ng3 = gumbel_one(kk, jbase + 3u);
        }

        // masked score at the sampled index (owner lane -> broadcast)
        int sub = nxt & 3;
        float sel = (sub == 0) ? mk0 : (sub == 1) ? mk1 : (sub == 2) ? mk2 : mk3;
        float pick = __shfl_sync(0xffffffffu, sel, nxt >> 2);

        // log-sum-exp over masked scores
        float e = expf(mk0 - mx) + expf(mk1 - mx) + expf(mk2 - mx) + expf(mk3 - mx);
#pragma unroll
        for (int o = 16; o > 0; o >>= 1) e += __shfl_xor_sync(0xffffffffu, e, o);

        logp += pick - mx - logf(e);
        if (lane == 0) out[b * 128 + t + 1] = (float)nxt;
        if ((nxt >> 2) == lane) visited |= 1u << sub;

        sc = scn;
        g0 = ng0; g1 = ng1; g2 = ng2; g3 = ng3;
    }
    if (lane == 0 && out_size >= 2048 * 128 + 2048) out[2048 * 128 + b] = logp;
}

extern "C" void kernel_launch(void* const* d_in, const int* in_sizes, int n_in,
                              void* d_out, int out_size) {
    const float* h     = (const float*)d_in[0];
    const float* graph = (const float*)d_in[1];
    const float* Wq    = (const float*)d_in[2];
    const float* bq    = (const float*)d_in[3];
    const float* Wk    = (const float*)d_in[4];
    const float* bk    = (const float*)d_in[5];
    const float* Wc    = (const float*)d_in[8];
    const float* bc    = (const float*)d_in[9];
    float* out = (float*)d_out;

    setup1_kernel<<<129, 128>>>(Wq, bq, Wk, bk);
    setup2_kernel<<<129, 128>>>(Wc);
    keys_kernel<<<1, 128>>>();
    cudaFuncSetAttribute(scores_kernel, cudaFuncAttributeMaxDynamicSharedMemorySize, SMEMB);
    scores_kernel<<<2048, 512, SMEMB>>>(h, graph, Wc, bc);
    decode_kernel<<<2048, 32>>>(out, out_size);
}

// round 16
// speedup vs baseline: 1.1901x; 1.0314x over previous
#include <cuda_runtime.h>
#include <stdint.h>
#include <stddef.h>
#include <math.h>

#define SMS 132
#define SMEMB (3 * 128 * SMS * 4)

__device__ double d_Ad[128 * 128];
__device__ float  d_Af[128 * 128];
__device__ float  d_W3[128 * 128];
__device__ double d_ud[128];
__device__ float  d_uf[128];
__device__ float  d_vf[128];
__device__ float  d_yf[128];
__device__ float  d_wf;
__device__ uint2  d_keys[127];
__device__ float  d_SC[2048u * 128u * 128u];      // scores [b][m][n]

__device__ __forceinline__ uint32_t rotl32(uint32_t v, uint32_t s) {
    return (v << s) | (v >> (32u - s));
}
__device__ __forceinline__ void tf2x32(uint32_t k0, uint32_t k1, uint32_t& x0, uint32_t& x1) {
    uint32_t k2 = k0 ^ k1 ^ 0x1BD11BDAu;
    x0 += k0; x1 += k1;
#define TFR(r) { x0 += x1; x1 = rotl32(x1, r); x1 ^= x0; }
    TFR(13u) TFR(15u) TFR(26u) TFR(6u)  x0 += k1; x1 += k2 + 1u;
    TFR(17u) TFR(29u) TFR(16u) TFR(24u) x0 += k2; x1 += k0 + 2u;
    TFR(13u) TFR(15u) TFR(26u) TFR(6u)  x0 += k0; x1 += k1 + 3u;
    TFR(17u) TFR(29u) TFR(16u) TFR(24u) x0 += k1; x1 += k2 + 4u;
    TFR(13u) TFR(15u) TFR(26u) TFR(6u)  x0 += k2; x1 += k0 + 5u;
#undef TFR
}

// partitionable random_bits (32-bit): bits = x0out ^ x1out of threefry(key, hi=0, lo=j)
__device__ __forceinline__ float gumbel_one(uint2 kk, uint32_t j) {
    uint32_t x0 = 0u, x1 = j;
    tf2x32(kk.x, kk.y, x0, x1);
    uint32_t bits = x0 ^ x1;
    const float TINY = 1.17549435082228751e-38f;
    float f = __uint_as_float((bits >> 9) | 0x3f800000u) - 1.0f;
    float u = fmaxf(TINY, f + TINY);
    return -logf(-logf(u));
}

// XLA EmitTanh rational approximation (f32)
__device__ __forceinline__ float xla_tanh(float x) {
    const float cl = 7.99881172180175781f;
    float xc = fminf(fmaxf(x, -cl), cl);
    float x2 = xc * xc;
    float p = fmaf(x2, -2.76076847742355e-16f, 2.00018790482477e-13f);
    p = fmaf(x2, p, -8.60467152213735e-11f);
    p = fmaf(x2, p,  5.12229709037114e-08f);
    p = fmaf(x2, p,  1.48572235717979e-05f);
    p = fmaf(x2, p,  6.37261928875436e-04f);
    p = fmaf(x2, p,  4.89352455891786e-03f);
    float num = xc * p;
    float q = fmaf(x2, 1.19825839466702e-06f, 1.18534705686654e-04f);
    q = fmaf(x2, q, 2.26843463243900e-03f);
    q = fmaf(x2, q, 4.89352518554385e-03f);
    float r = num / q;
    return (fabsf(x) < 0.0004f) ? x : r;
}

#define KAHAN(s, c0, prod) { float _y = (prod) - (c0); float _t = (s) + _y; (c0) = (_t - (s)) - _y; (s) = _t; }

typedef unsigned long long u64t;
__device__ __forceinline__ u64t pk2(float lo, float hi) {
    u64t r; asm("mov.b64 %0,{%1,%2};" : "=l"(r) : "f"(lo), "f"(hi)); return r;
}
__device__ __forceinline__ u64t fma2(u64t a, u64t b, u64t c) {
    u64t d; asm("fma.rn.f32x2 %0,%1,%2,%3;" : "=l"(d) : "l"(a), "l"(b), "l"(c)); return d;
}
__device__ __forceinline__ void upk2(u64t v, float& lo, float& hi) {
    asm("mov.b64 {%0,%1},%2;" : "=f"(lo), "=f"(hi) : "l"(v));
}

// 4-chain Kahan dot over 128 elems: accuracy ~Kahan, latency ~1/4 (ILP 4).
__device__ __forceinline__ float kdot128(const float* __restrict__ a, int astride,
                                         const float* __restrict__ b, int bstride) {
    float s0 = 0.f, s1 = 0.f, s2 = 0.f, s3 = 0.f;
    float c0 = 0.f, c1 = 0.f, c2 = 0.f, c3 = 0.f;
#pragma unroll 4
    for (int i = 0; i < 128; i += 4) {
        float p0 = a[(i + 0) * astride] * b[(i + 0) * bstride];
        float p1 = a[(i + 1) * astride] * b[(i + 1) * bstride];
        float p2 = a[(i + 2) * astride] * b[(i + 2) * bstride];
        float p3 = a[(i + 3) * astride] * b[(i + 3) * bstride];
        KAHAN(s0, c0, p0) KAHAN(s1, c1, p1) KAHAN(s2, c2, p2) KAHAN(s3, c3, p3)
    }
    return (s0 + s1) + (s2 + s3);
}

// partitionable (foldlike) split: key[t] = (x0out, x1out) = threefry(key, hi=0, lo=t)
__global__ void keys_kernel() {
    int t = threadIdx.x;
    if (t < 127) {
        uint32_t x0 = 0u, x1 = (uint32_t)t;
        tf2x32(0u, 42u, x0, x1);
        d_keys[t] = make_uint2(x0, x1);
    }
}

__global__ void setup1_kernel(const float* __restrict__ Wq, const float* __restrict__ bq,
                              const float* __restrict__ Wk, const float* __restrict__ bk) {
    int blk = blockIdx.x, t = threadIdx.x;
    if (blk < 128) {
        const float* wqr = Wq + blk * 128;
        const float* wkr = Wk + t * 128;
        double s = 0.0;
        for (int j = 0; j < 128; j++) s += (double)wqr[j] * (double)wkr[j];
        d_Ad[blk * 128 + t] = s;
        d_Af[blk * 128 + t] = (float)s;
    } else {
        double su = 0.0, sv = 0.0;
        for (int j = 0; j < 128; j++) {
            su += (double)Wq[t * 128 + j] * (double)bk[j];
            sv += (double)bq[j] * (double)Wk[t * 128 + j];
        }
        d_ud[t] = su; d_uf[t] = (float)su; d_vf[t] = (float)sv;
        if (t == 0) {
            double sw = 0.0;
            for (int j = 0; j < 128; j++) sw += (double)bq[j] * (double)bk[j];
            d_wf = (float)sw;
        }
    }
}

__global__ void setup2_kernel(const float* __restrict__ Wc) {
    int blk = blockIdx.x, t = threadIdx.x;
    if (blk < 128) {
        const float* wcr = Wc + (128 + blk) * 128;
        double s = 0.0;
        for (int j = 0; j < 128; j++) s += (double)wcr[j] * d_Ad[j * 128 + t];
        d_W3[blk * 128 + t] = (float)s;
    } else {
        const float* wcr = Wc + (128 + t) * 128;
        double s = 0.0;
        for (int j = 0; j < 128; j++) s += (double)wcr[j] * d_ud[j];
        d_yf[t] = (float)s;
    }
}

// 512 threads, 16 warps. Per thread: 8 rows x 4 cols of the 128x128 output.
// tx = tid & 31 -> col block (c0 = tx*4), ty = tid >> 5 -> row block (r0 = ty*8).
// A strip loaded as double2 (natural f32x2 pairs, zero-cost repack);
// B scalars duplicated into both halves (4 MOVs per k-step).
// acc[jp][n]: jp = row-pair (rows r0+2jp, r0+2jp+1), n = col c0+n.
__global__ void __launch_bounds__(512, 1) scores_kernel(
    const float* __restrict__ h, const float* __restrict__ graph,
    const float* __restrict__ Wc, const float* __restrict__ bc)
{
    extern __shared__ float smem[];
    float* hT  = smem;                 // hT[l][n] = h[b][n][l]
    float* W3s = smem + 128 * SMS;     // W3 row-major [k][l]
    float* Gt  = smem + 2 * 128 * SMS; // Gt[l][m] = G[m][l]
    __shared__ float Psh[128], PAsh[128], Ssh[128], Rsh[128];
    __shared__ float cbsh;

    const int b = blockIdx.x, tid = threadIdx.x;
    const int tx = tid & 31, ty = tid >> 5;
    const int r0 = ty << 3, c0 = tx << 2;
    const float* __restrict__ hb = h + ((size_t)b << 14);

    {   // load h transposed (512 threads: 128 rows x 4 chunks of 32 floats)
        int row = tid >> 2, cb0 = (tid & 3) << 5;
        const float4* src = (const float4*)(hb + row * 128 + cb0);
#pragma unroll
        for (int q = 0; q < 8; q++) {
            float4 vv = src[q];
            int l = cb0 + 4 * q;
            hT[(l + 0) * SMS + row] = vv.x; hT[(l + 1) * SMS + row] = vv.y;
            hT[(l + 2) * SMS + row] = vv.z; hT[(l + 3) * SMS + row] = vv.w;
        }
        const float4* w3 = (const float4*)d_W3;
        for (int i = tid; i < 128 * 32; i += 512) {
            float4 vv = w3[i];
            *(float4*)&W3s[(i >> 5) * SMS + ((i & 31) << 2)] = vv;
        }
    }
    __syncthreads();

    if (tid < 128) {    // P[j] = graph_b . Wc_top[:,j] + bc[j]
        Psh[tid] = kdot128(graph + (b << 7), 1, Wc + tid, 128) + bc[tid];
    }
    __syncthreads();
    if (tid < 128) {    // PA[l] + v[l]
        PAsh[tid] = kdot128(Psh, 1, d_Af + tid, 128) + d_vf[tid];
    } else if (tid == 128) {
        cbsh = kdot128(Psh, 1, d_uf, 1) + d_wf;
    }
    __syncthreads();
    if (tid < 128) {    // S[n]
        Ssh[tid] = kdot128(PAsh, 1, hT + tid, SMS);
    } else if (tid < 256) {  // R[m]
        int m = tid - 128;
        Rsh[m] = kdot128(d_yf, 1, hT + m, SMS) + cbsh;
    }
    __syncthreads();

    u64t acc[4][4];
#pragma unroll
    for (int jp = 0; jp < 4; jp++)
#pragma unroll
        for (int n = 0; n < 4; n++) acc[jp][n] = 0ull;

    // phase 1: Gt[l][m] = sum_k W3s[k][l] * hT[k][m]   (l = r0..r0+7, m = c0..c0+3)
#pragma unroll 8
    for (int k = 0; k < 128; k++) {
        double2 A01 = *(const double2*)&W3s[k * SMS + r0];
        double2 A23 = *(const double2*)&W3s[k * SMS + r0 + 4];
        float4  B   = *(const float4*)&hT[k * SMS + c0];
        u64t pa0 = __double_as_longlong(A01.x);
        u64t pa1 = __double_as_longlong(A01.y);
        u64t pa2 = __double_as_longlong(A23.x);
        u64t pa3 = __double_as_longlong(A23.y);
        u64t pb0 = pk2(B.x, B.x), pb1 = pk2(B.y, B.y);
        u64t pb2 = pk2(B.z, B.z), pb3 = pk2(B.w, B.w);
        acc[0][0] = fma2(pa0, pb0, acc[0][0]); acc[0][1] = fma2(pa0, pb1, acc[0][1]);
        acc[0][2] = fma2(pa0, pb2, acc[0][2]); acc[0][3] = fma2(pa0, pb3, acc[0][3]);
        acc[1][0] = fma2(pa1, pb0, acc[1][0]); acc[1][1] = fma2(pa1, pb1, acc[1][1]);
        acc[1][2] = fma2(pa1, pb2, acc[1][2]); acc[1][3] = fma2(pa1, pb3, acc[1][3]);
        acc[2][0] = fma2(pa2, pb0, acc[2][0]); acc[2][1] = fma2(pa2, pb1, acc[2][1]);
        acc[2][2] = fma2(pa2, pb2, acc[2][2]); acc[2][3] = fma2(pa2, pb3, acc[2][3]);
        acc[3][0] = fma2(pa3, pb0, acc[3][0]); acc[3][1] = fma2(pa3, pb1, acc[3][1]);
        acc[3][2] = fma2(pa3, pb2, acc[3][2]); acc[3][3] = fma2(pa3, pb3, acc[3][3]);
    }
#pragma unroll
    for (int jp = 0; jp < 4; jp++) {
        float lo0, hi0, lo1, hi1, lo2, hi2, lo3, hi3;
        upk2(acc[jp][0], lo0, hi0); upk2(acc[jp][1], lo1, hi1);
        upk2(acc[jp][2], lo2, hi2); upk2(acc[jp][3], lo3, hi3);
        *(float4*)&Gt[(r0 + 2 * jp)     * SMS + c0] = make_float4(lo0, lo1, lo2, lo3);
        *(float4*)&Gt[(r0 + 2 * jp + 1) * SMS + c0] = make_float4(hi0, hi1, hi2, hi3);
    }
    __syncthreads();

#pragma unroll
    for (int jp = 0; jp < 4; jp++)
#pragma unroll
        for (int n = 0; n < 4; n++) acc[jp][n] = 0ull;

    // phase 2: pair[m][n] = sum_l Gt[l][m] * hT[l][n]   (m = r0..r0+7, n = c0..c0+3)
#pragma unroll 8
    for (int l = 0; l < 128; l++) {
        double2 A01 = *(const double2*)&Gt[l * SMS + r0];
        double2 A23 = *(const double2*)&Gt[l * SMS + r0 + 4];
        float4  B   = *(const float4*)&hT[l * SMS + c0];
        u64t pa0 = __double_as_longlong(A01.x);
        u64t pa1 = __double_as_longlong(A01.y);
        u64t pa2 = __double_as_longlong(A23.x);
        u64t pa3 = __double_as_longlong(A23.y);
        u64t pb0 = pk2(B.x, B.x), pb1 = pk2(B.y, B.y);
        u64t pb2 = pk2(B.z, B.z), pb3 = pk2(B.w, B.w);
        acc[0][0] = fma2(pa0, pb0, acc[0][0]); acc[0][1] = fma2(pa0, pb1, acc[0][1]);
        acc[0][2] = fma2(pa0, pb2, acc[0][2]); acc[0][3] = fma2(pa0, pb3, acc[0][3]);
        acc[1][0] = fma2(pa1, pb0, acc[1][0]); acc[1][1] = fma2(pa1, pb1, acc[1][1]);
        acc[1][2] = fma2(pa1, pb2, acc[1][2]); acc[1][3] = fma2(pa1, pb3, acc[1][3]);
        acc[2][0] = fma2(pa2, pb0, acc[2][0]); acc[2][1] = fma2(pa2, pb1, acc[2][1]);
        acc[2][2] = fma2(pa2, pb2, acc[2][2]); acc[2][3] = fma2(pa2, pb3, acc[2][3]);
        acc[3][0] = fma2(pa3, pb0, acc[3][0]); acc[3][1] = fma2(pa3, pb1, acc[3][1]);
        acc[3][2] = fma2(pa3, pb2, acc[3][2]); acc[3][3] = fma2(pa3, pb3, acc[3][3]);
    }

    float* scb = d_SC + ((size_t)b << 14);
    float s0 = Ssh[c0], s1 = Ssh[c0 + 1], s2 = Ssh[c0 + 2], s3 = Ssh[c0 + 3];
#pragma unroll
    for (int jp = 0; jp < 4; jp++) {
        int m0 = r0 + 2 * jp, m1 = m0 + 1;
        float rr0 = Rsh[m0], rr1 = Rsh[m1];
        float lo0, hi0, lo1, hi1, lo2, hi2, lo3, hi3;
        upk2(acc[jp][0], lo0, hi0); upk2(acc[jp][1], lo1, hi1);
        upk2(acc[jp][2], lo2, hi2); upk2(acc[jp][3], lo3, hi3);
        float4 o0, o1;
        o0.x = 10.0f * xla_tanh((lo0 + (rr0 + s0)) * 0.03125f);
        o0.y = 10.0f * xla_tanh((lo1 + (rr0 + s1)) * 0.03125f);
        o0.z = 10.0f * xla_tanh((lo2 + (rr0 + s2)) * 0.03125f);
        o0.w = 10.0f * xla_tanh((lo3 + (rr0 + s3)) * 0.03125f);
        o1.x = 10.0f * xla_tanh((hi0 + (rr1 + s0)) * 0.03125f);
        o1.y = 10.0f * xla_tanh((hi1 + (rr1 + s1)) * 0.03125f);
        o1.z = 10.0f * xla_tanh((hi2 + (rr1 + s2)) * 0.03125f);
        o1.w = 10.0f * xla_tanh((hi3 + (rr1 + s3)) * 0.03125f);
        *(float4*)&scb[m0 * 128 + c0] = o0;
        *(float4*)&scb[m1 * 128 + c0] = o1;
    }
}

// Single-warp decode: 32 threads, 4 nodes each; no __syncthreads.
// Gumbel noise computed inline (threefry), pipelined under the score-row load.
__global__ void __launch_bounds__(32) decode_kernel(float* __restrict__ out, int out_size) {
    const int b = blockIdx.x;
    const int lane = threadIdx.x;
    const float NEG = __int_as_float(0xff800000);
    const float* __restrict__ scRow = d_SC + ((size_t)b << 14);

    unsigned visited = (lane == 0) ? 1u : 0u;       // bit i <-> node lane*4+i
    float logp = 0.0f;
    if (lane == 0) out[b * 128] = 0.0f;

    const uint32_t jbase = ((uint32_t)b << 7) + ((uint32_t)lane << 2);
    const int nbase = lane << 2;

    float4 sc = *(const float4*)(scRow + nbase);     // row of cur = 0
    float g0, g1, g2, g3;
    {
        uint2 kk = d_keys[0];
        g0 = gumbel_one(kk, jbase + 0u);
        g1 = gumbel_one(kk, jbase + 1u);
        g2 = gumbel_one(kk, jbase + 2u);
        g3 = gumbel_one(kk, jbase + 3u);
    }

    for (int t = 0; t < 127; t++) {
        float mk0 = (visited & 1u) ? NEG : sc.x;
        float mk1 = (visited & 2u) ? NEG : sc.y;
        float mk2 = (visited & 4u) ? NEG : sc.z;
        float mk3 = (visited & 8u) ? NEG : sc.w;

        // local argmax of mk+g (first index wins on ties via strict >)
        float v = mk0 + g0; int idx = nbase;
        float c;
        c = mk1 + g1; if (c > v) { v = c; idx = nbase + 1; }
        c = mk2 + g2; if (c > v) { v = c; idx = nbase + 2; }
        c = mk3 + g3; if (c > v) { v = c; idx = nbase + 3; }
        float mm = fmaxf(fmaxf(mk0, mk1), fmaxf(mk2, mk3));

#pragma unroll
        for (int o = 16; o > 0; o >>= 1) {
            float ov = __shfl_xor_sync(0xffffffffu, v, o);
            int   oi = __shfl_xor_sync(0xffffffffu, idx, o);
            float om = __shfl_xor_sync(0xffffffffu, mm, o);
            if (ov > v || (ov == v && oi < idx)) { v = ov; idx = oi; }
            mm = fmaxf(mm, om);
        }
        const int nxt = idx;           // identical across lanes after butterfly
        const float mx = mm;

        // prefetch next score row (dominant latency; below ALU overlaps it)
        float4 scn = *(const float4*)(scRow + (nxt << 7) + nbase);

        // next-step gumbel, computed under the load
        float ng0 = 0.f, ng1 = 0.f, ng2 = 0.f, ng3 = 0.f;
        if (t < 126) {
            uint2 kk = d_keys[t + 1];
            ng0 = gumbel_one(kk, jbase + 0u);
            ng1 = gumbel_one(kk, jbase + 1u);
            ng2 = gumbel_one(kk, jbase + 2u);
            ng3 = gumbel_one(kk, jbase + 3u);
        }

        // masked score at the sampled index (owner lane -> broadcast)
        int sub = nxt & 3;
        float sel = (sub == 0) ? mk0 : (sub == 1) ? mk1 : (sub == 2) ? mk2 : mk3;
        float pick = __shfl_sync(0xffffffffu, sel, nxt >> 2);

        // log-sum-exp over masked scores
        float e = expf(mk0 - mx) + expf(mk1 - mx) + expf(mk2 - mx) + expf(mk3 - mx);
#pragma unroll
        for (int o = 16; o > 0; o >>= 1) e += __shfl_xor_sync(0xffffffffu, e, o);

        logp += pick - mx - logf(e);
        if (lane == 0) out[b * 128 + t + 1] = (float)nxt;
        if ((nxt >> 2) == lane) visited |= 1u << sub;

        sc = scn;
        g0 = ng0; g1 = ng1; g2 = ng2; g3 = ng3;
    }
    if (lane == 0 && out_size >= 2048 * 128 + 2048) out[2048 * 128 + b] = logp;
}

extern "C" void kernel_launch(void* const* d_in, const int* in_sizes, int n_in,
                              void* d_out, int out_size) {
    const float* h     = (const float*)d_in[0];
    const float* graph = (const float*)d_in[1];
    const float* Wq    = (const float*)d_in[2];
    const float* bq    = (const float*)d_in[3];
    const float* Wk    = (const float*)d_in[4];
    const float* bk    = (const float*)d_in[5];
    const float* Wc    = (const float*)d_in[8];
    const float* bc    = (const float*)d_in[9];
    float* out = (float*)d_out;

    setup1_kernel<<<129, 128>>>(Wq, bq, Wk, bk);
    setup2_kernel<<<129, 128>>>(Wc);
    keys_kernel<<<1, 128>>>();
    cudaFuncSetAttribute(scores_kernel, cudaFuncAttributeMaxDynamicSharedMemorySize, SMEMB);
    scores_kernel<<<2048, 512, SMEMB>>>(h, graph, Wc, bc);
    decode_kernel<<<2048, 32>>>(out, out_size);
}